// round 15
// baseline (speedup 1.0000x reference)
#include <cuda_runtime.h>
#include <cuda_fp16.h>
#include <cstdint>

// Problem dims
#define DIMC 2048
#define TT   2048
#define MROWS 16384            // B*T = 8*2048

// ---------------- scratch (static device globals; no dynamic alloc) ----------
__device__ __half g_hxr[33554432];   // mixed activations / wkv z
__device__ __half g_hxk[33554432];
__device__ __half g_hxv[33554432];
__device__ __half g_hr [33554432];   // GEMM outputs r / r2
__device__ __half g_hk [33554432];   // GEMM outputs k / relu(k2)^2
__device__ __half g_hv [33554432];   // GEMM output v
__device__ __half g_wh [7 * 4194304];   // 7 fp16 weight matrices

// ---------------- helpers ----------------------------------------------------
__device__ __forceinline__ uint32_t smem_u32(const void* p) {
    return (uint32_t)__cvta_generic_to_shared(p);
}
__device__ __forceinline__ void cp_async16(uint32_t saddr, const void* gptr) {
    asm volatile("cp.async.cg.shared.global [%0], [%1], 16;\n" :: "r"(saddr), "l"(gptr));
}
__device__ __forceinline__ float sigmoidf_(float x) {
    return 1.0f / (1.0f + expf(-x));
}
__device__ __forceinline__ uint32_t pack_h2(float a, float b) {
    __half2 h = __floats2half2_rn(a, b);
    return *(uint32_t*)&h;
}

// ---------------- fused LayerNorm + token-shift mix ---------------------------
template<int NOUT>
__global__ __launch_bounds__(256) void lnmix_kernel(
    const float* __restrict__ x, const float* __restrict__ g,
    const float* __restrict__ b,
    const float* __restrict__ mur, const float* __restrict__ muk,
    const float* __restrict__ muv,
    __half* __restrict__ xr, __half* __restrict__ xk, __half* __restrict__ xv)
{
    __shared__ float sred[32];
    int row = blockIdx.x;
    int tid = threadIdx.x;
    int t = row & (TT - 1);

    const float4* xp = (const float4*)(x + (size_t)row * DIMC);
    float4 v0 = xp[tid];
    float4 v1 = xp[tid + 256];
    float4 w0 = make_float4(0.f,0.f,0.f,0.f), w1 = w0;
    if (t > 0) {
        const float4* xq = (const float4*)(x + (size_t)(row - 1) * DIMC);
        w0 = xq[tid];
        w1 = xq[tid + 256];
    }
    float s0  = v0.x+v0.y+v0.z+v0.w + v1.x+v1.y+v1.z+v1.w;
    float ss0 = v0.x*v0.x+v0.y*v0.y+v0.z*v0.z+v0.w*v0.w
              + v1.x*v1.x+v1.y*v1.y+v1.z*v1.z+v1.w*v1.w;
    float s1  = w0.x+w0.y+w0.z+w0.w + w1.x+w1.y+w1.z+w1.w;
    float ss1 = w0.x*w0.x+w0.y*w0.y+w0.z*w0.z+w0.w*w0.w
              + w1.x*w1.x+w1.y*w1.y+w1.z*w1.z+w1.w*w1.w;
    #pragma unroll
    for (int o = 16; o > 0; o >>= 1) {
        s0  += __shfl_xor_sync(0xffffffffu, s0,  o);
        ss0 += __shfl_xor_sync(0xffffffffu, ss0, o);
        s1  += __shfl_xor_sync(0xffffffffu, s1,  o);
        ss1 += __shfl_xor_sync(0xffffffffu, ss1, o);
    }
    int wid = tid >> 5;
    if ((tid & 31) == 0) {
        sred[wid] = s0; sred[wid + 8] = ss0;
        sred[wid + 16] = s1; sred[wid + 24] = ss1;
    }
    __syncthreads();
    if (tid < 32) {
        float a = (tid < 8) ? sred[tid]      : 0.f;
        float c = (tid < 8) ? sred[tid + 8]  : 0.f;
        float d = (tid < 8) ? sred[tid + 16] : 0.f;
        float e = (tid < 8) ? sred[tid + 24] : 0.f;
        #pragma unroll
        for (int o = 4; o > 0; o >>= 1) {
            a += __shfl_xor_sync(0xffffffffu, a, o);
            c += __shfl_xor_sync(0xffffffffu, c, o);
            d += __shfl_xor_sync(0xffffffffu, d, o);
            e += __shfl_xor_sync(0xffffffffu, e, o);
        }
        if (tid == 0) { sred[0] = a; sred[1] = c; sred[2] = d; sred[3] = e; }
    }
    __syncthreads();
    float m0 = sred[0] * (1.0f / DIMC);
    float r0 = rsqrtf(sred[1] * (1.0f / DIMC) - m0 * m0 + 1e-5f);
    float m1 = sred[2] * (1.0f / DIMC);
    float r1 = rsqrtf(sred[3] * (1.0f / DIMC) - m1 * m1 + 1e-5f);
    float pf = (t > 0) ? 1.0f : 0.0f;   // hp = 0 at t==0

    const float4* gp = (const float4*)g;
    const float4* bp = (const float4*)b;
    uint2* xr2 = (uint2*)(xr + (size_t)row * DIMC);
    uint2* xk2 = (uint2*)(xk + (size_t)row * DIMC);
    uint2* xv2 = (uint2*)(xv + (size_t)row * DIMC);

    #pragma unroll
    for (int half_ = 0; half_ < 2; half_++) {
        int idx = tid + half_ * 256;
        float4 vv = half_ ? v1 : v0;
        float4 ww = half_ ? w1 : w0;
        float4 gg = gp[idx], bb = bp[idx];
        float4 h, hp;
        h.x = (vv.x - m0) * r0 * gg.x + bb.x;
        h.y = (vv.y - m0) * r0 * gg.y + bb.y;
        h.z = (vv.z - m0) * r0 * gg.z + bb.z;
        h.w = (vv.w - m0) * r0 * gg.w + bb.w;
        hp.x = ((ww.x - m1) * r1 * gg.x + bb.x) * pf;
        hp.y = ((ww.y - m1) * r1 * gg.y + bb.y) * pf;
        hp.z = ((ww.z - m1) * r1 * gg.z + bb.z) * pf;
        hp.w = ((ww.w - m1) * r1 * gg.w + bb.w) * pf;
        float4 mu, o;
        mu = ((const float4*)mur)[idx];
        o.x = mu.x*h.x + (1.f-mu.x)*hp.x;  o.y = mu.y*h.y + (1.f-mu.y)*hp.y;
        o.z = mu.z*h.z + (1.f-mu.z)*hp.z;  o.w = mu.w*h.w + (1.f-mu.w)*hp.w;
        xr2[idx] = make_uint2(pack_h2(o.x, o.y), pack_h2(o.z, o.w));
        mu = ((const float4*)muk)[idx];
        o.x = mu.x*h.x + (1.f-mu.x)*hp.x;  o.y = mu.y*h.y + (1.f-mu.y)*hp.y;
        o.z = mu.z*h.z + (1.f-mu.z)*hp.z;  o.w = mu.w*h.w + (1.f-mu.w)*hp.w;
        xk2[idx] = make_uint2(pack_h2(o.x, o.y), pack_h2(o.z, o.w));
        if (NOUT == 3) {
            mu = ((const float4*)muv)[idx];
            o.x = mu.x*h.x + (1.f-mu.x)*hp.x;  o.y = mu.y*h.y + (1.f-mu.y)*hp.y;
            o.z = mu.z*h.z + (1.f-mu.z)*hp.z;  o.w = mu.w*h.w + (1.f-mu.w)*hp.w;
            xv2[idx] = make_uint2(pack_h2(o.x, o.y), pack_h2(o.z, o.w));
        }
    }
}

// ---------------- wkv: z = sigmoid(r) * (e^{u+k} v)/(e^{u+k}+1e-8), all fp16 --
__global__ __launch_bounds__(256) void wkv_kernel(
    const __half* __restrict__ r, const __half* __restrict__ k,
    const __half* __restrict__ v, const float* __restrict__ u,
    __half* __restrict__ z)
{
    size_t i = (size_t)blockIdx.x * 256 + threadIdx.x;   // uint2 = 4 halves
    uint2 ru = ((const uint2*)r)[i];
    uint2 ku = ((const uint2*)k)[i];
    uint2 vu = ((const uint2*)v)[i];
    int c4 = (int)(i & 511);
    float4 uv = ((const float4*)u)[c4];
    float2 ra = __half22float2(*(__half2*)&ru.x), rb = __half22float2(*(__half2*)&ru.y);
    float2 ka = __half22float2(*(__half2*)&ku.x), kb = __half22float2(*(__half2*)&ku.y);
    float2 va = __half22float2(*(__half2*)&vu.x), vb = __half22float2(*(__half2*)&vu.y);
    float4 o;
    { float ek = expf(uv.x + ka.x); o.x = sigmoidf_(ra.x) * (ek * va.x) / (ek + 1e-8f); }
    { float ek = expf(uv.y + ka.y); o.y = sigmoidf_(ra.y) * (ek * va.y) / (ek + 1e-8f); }
    { float ek = expf(uv.z + kb.x); o.z = sigmoidf_(rb.x) * (ek * vb.x) / (ek + 1e-8f); }
    { float ek = expf(uv.w + kb.y); o.w = sigmoidf_(rb.y) * (ek * vb.y) / (ek + 1e-8f); }
    ((uint2*)z)[i] = make_uint2(pack_h2(o.x, o.y), pack_h2(o.z, o.w));
}

// ---------------- weight prep: fp32 -> fp16, all 7 matrices in one launch -----
struct WP { const float* s[7]; __half* d[7]; };
__global__ __launch_bounds__(256) void wprep_kernel(WP wp)
{
    int m = blockIdx.y;
    size_t i = (size_t)blockIdx.x * 256 + threadIdx.x;
    float4 v = ((const float4*)wp.s[m])[i];
    ((uint2*)wp.d[m])[i] = make_uint2(pack_h2(v.x, v.y), pack_h2(v.z, v.w));
}

// ---------------- fp16 GEMM: C[m,n] = sum_k A[m,k] * W[n,k] -------------------
// Block tile 128M x 256N, 16 warps (512 thr), warp tile 32x64.
// K-chunk 64 halves (128B SW128 rows), 4-stage cp.async ring with a SINGLE
// __syncthreads per chunk (issue targets slot (c+3)%4 != c%4, ordered by the
// barrier). ldmatrix.x4 feed, mma.sync.m16n8k16.f16.f32.
// gridDim.z batches independent GEMMs.
// MODE 0: C[z] = half(acc)
// MODE 1: C[0] = auxf + acc  (fp32)
// MODE 2: C[0] += sigmoid(auxh)*acc (fp32, in place)
// MODE 3: z==0: half(acc) ; z==1: half(relu(acc)^2)

#define KCH 64
#define NCCH (DIMC / KCH)           // 32 chunks
#define ASTG (128 * 128)            // 16 KB
#define BSTG (256 * 128)            // 32 KB
#define STGB (ASTG + BSTG)          // 48 KB
#define GSM  (4 * STGB)             // 192 KB

struct GB {
    const __half* A[3];
    const __half* W[3];
    void* C[3];
    const void* aux;
};

#define LDMX4(r0, r1, r2, r3, a) \
    asm volatile("ldmatrix.sync.aligned.m8n8.x4.shared.b16 {%0,%1,%2,%3}, [%4];" \
        : "=r"(r0), "=r"(r1), "=r"(r2), "=r"(r3) : "r"(a))

#define MMA16816(acc, a, b0, b1) \
    asm volatile( \
        "mma.sync.aligned.m16n8k16.row.col.f32.f16.f16.f32 " \
        "{%0,%1,%2,%3},{%4,%5,%6,%7},{%8,%9},{%0,%1,%2,%3};\n" \
        : "+f"((acc)[0]), "+f"((acc)[1]), "+f"((acc)[2]), "+f"((acc)[3]) \
        : "r"((a)[0]), "r"((a)[1]), "r"((a)[2]), "r"((a)[3]), "r"(b0), "r"(b1))

template<int MODE>
__global__ __launch_bounds__(512, 1) void gemm_h(GB gb)
{
    extern __shared__ char dsm[];
    uint32_t base = smem_u32(dsm);
    int tid  = threadIdx.x;
    int ln   = tid & 31;
    int wid  = tid >> 5;
    int z  = blockIdx.z;
    int bm = blockIdx.x * 128;
    int bn = blockIdx.y * 256;
    int mwarp = (wid & 3) * 32;
    int nwarp = (wid >> 2) * 64;

    const __half* A = gb.A[z];
    const __half* W = gb.W[z];

    float acc[2][8][4];
    #pragma unroll
    for (int i = 0; i < 2; i++)
        #pragma unroll
        for (int j = 0; j < 8; j++)
            #pragma unroll
            for (int q = 0; q < 4; q++) acc[i][j][q] = 0.f;

    auto issue = [&](int c) {
        uint32_t sb = base + (c & 3) * STGB;
        int kofs = c * KCH;
        #pragma unroll
        for (int j = 0; j < 2; j++) {          // A: 1024 segments
            int ch = tid + j * 512;
            int row = ch >> 3, seg = ch & 7;
            uint32_t off = row * 128 + seg * 16;
            uint32_t sw = off ^ ((off >> 3) & 0x70);
            cp_async16(sb + sw, A + (size_t)(bm + row) * DIMC + kofs + seg * 8);
        }
        #pragma unroll
        for (int j = 0; j < 4; j++) {          // B: 2048 segments
            int ch = tid + j * 512;
            int row = ch >> 3, seg = ch & 7;
            uint32_t off = row * 128 + seg * 16;
            uint32_t sw = off ^ ((off >> 3) & 0x70);
            cp_async16(sb + ASTG + sw, W + (size_t)(bn + row) * DIMC + kofs + seg * 8);
        }
        asm volatile("cp.async.commit_group;\n" ::: "memory");
    };

    issue(0); issue(1); issue(2);

    int t4 = ln >> 3, r8 = ln & 7;
    int rA = (t4 & 1) * 8 + r8;
    int kA = (t4 >> 1) * 16;
    int rB = (t4 >> 1) * 8 + r8;
    int kB = (t4 & 1) * 16;

    for (int c = 0; c < NCCH; c++) {
        if (c <= NCCH - 3)      asm volatile("cp.async.wait_group 2;\n" ::: "memory");
        else if (c == NCCH - 2) asm volatile("cp.async.wait_group 1;\n" ::: "memory");
        else                    asm volatile("cp.async.wait_group 0;\n" ::: "memory");
        __syncthreads();
        if (c + 3 < NCCH) issue(c + 3);   // slot (c+3)&3 != c&3: safe after barrier

        uint32_t sb = base + (c & 3) * STGB;
        uint32_t ab = sb, bb = sb + ASTG;

        #pragma unroll
        for (int ks = 0; ks < 4; ks++) {
            uint32_t av[2][4];
            #pragma unroll
            for (int mt = 0; mt < 2; mt++) {
                int row = mwarp + mt * 16 + rA;
                uint32_t off = row * 128 + ks * 32 + kA;
                uint32_t sw = off ^ ((off >> 3) & 0x70);
                LDMX4(av[mt][0], av[mt][1], av[mt][2], av[mt][3], ab + sw);
            }
            uint32_t bv[4][4];
            #pragma unroll
            for (int np = 0; np < 4; np++) {
                int row = nwarp + np * 16 + rB;
                uint32_t off = row * 128 + ks * 32 + kB;
                uint32_t sw = off ^ ((off >> 3) & 0x70);
                LDMX4(bv[np][0], bv[np][1], bv[np][2], bv[np][3], bb + sw);
            }
            #pragma unroll
            for (int nt = 0; nt < 8; nt++) {
                uint32_t b0 = bv[nt >> 1][(nt & 1) * 2 + 0];
                uint32_t b1 = bv[nt >> 1][(nt & 1) * 2 + 1];
                MMA16816(acc[0][nt], av[0], b0, b1);
                MMA16816(acc[1][nt], av[1], b0, b1);
            }
        }
    }

    // ---------------- epilogue ----------------
    int rbase = bm + mwarp + (ln >> 2);
    int cbase = bn + nwarp + (ln & 3) * 2;
    #pragma unroll
    for (int mt = 0; mt < 2; mt++) {
        #pragma unroll
        for (int nt = 0; nt < 8; nt++) {
            int r0 = rbase + mt * 16;
            int cc = cbase + nt * 8;
            size_t i0 = (size_t)r0 * DIMC + cc;
            size_t i1 = i0 + (size_t)8 * DIMC;
            float2 p0 = make_float2(acc[mt][nt][0], acc[mt][nt][1]);
            float2 p1 = make_float2(acc[mt][nt][2], acc[mt][nt][3]);
            if (MODE == 0 || MODE == 3) {
                __half* Ch = (__half*)gb.C[z];
                if (MODE == 3 && z == 1) {
                    float a0 = fmaxf(p0.x, 0.f), a1 = fmaxf(p0.y, 0.f);
                    float a2 = fmaxf(p1.x, 0.f), a3 = fmaxf(p1.y, 0.f);
                    p0 = make_float2(a0 * a0, a1 * a1);
                    p1 = make_float2(a2 * a2, a3 * a3);
                }
                *(__half2*)(Ch + i0) = __floats2half2_rn(p0.x, p0.y);
                *(__half2*)(Ch + i1) = __floats2half2_rn(p1.x, p1.y);
            } else if (MODE == 1) {
                float* Cf = (float*)gb.C[0];
                const float* auxf = (const float*)gb.aux;
                float2 a0 = *(const float2*)(auxf + i0);
                float2 a1 = *(const float2*)(auxf + i1);
                p0.x += a0.x; p0.y += a0.y;
                p1.x += a1.x; p1.y += a1.y;
                *(float2*)(Cf + i0) = p0;
                *(float2*)(Cf + i1) = p1;
            } else {
                float* Cf = (float*)gb.C[0];
                const __half* auxh = (const __half*)gb.aux;
                float2 a0 = __half22float2(*(const __half2*)(auxh + i0));
                float2 a1 = __half22float2(*(const __half2*)(auxh + i1));
                float2 c0 = *(const float2*)(Cf + i0);
                float2 c1 = *(const float2*)(Cf + i1);
                p0.x = c0.x + sigmoidf_(a0.x) * p0.x;
                p0.y = c0.y + sigmoidf_(a0.y) * p0.y;
                p1.x = c1.x + sigmoidf_(a1.x) * p1.x;
                p1.y = c1.y + sigmoidf_(a1.y) * p1.y;
                *(float2*)(Cf + i0) = p0;
                *(float2*)(Cf + i1) = p1;
            }
        }
    }
}

// ---------------- host orchestration -----------------------------------------
extern "C" void kernel_launch(void* const* d_in, const int* in_sizes, int n_in,
                              void* d_out, int out_size)
{
    const float* x    = (const float*)d_in[0];
    const float* ln1g = (const float*)d_in[1];
    const float* ln1b = (const float*)d_in[2];
    const float* ln2g = (const float*)d_in[3];
    const float* ln2b = (const float*)d_in[4];
    // d_in[5] = tm_w (unused by the reference semantics)
    const float* tmu  = (const float*)d_in[6];
    const float* tmur = (const float*)d_in[7];
    const float* tmuk = (const float*)d_in[8];
    const float* tmuv = (const float*)d_in[9];
    const float* tWr  = (const float*)d_in[10];
    const float* tWk  = (const float*)d_in[11];
    const float* tWv  = (const float*)d_in[12];
    const float* tWo  = (const float*)d_in[13];
    const float* cmur = (const float*)d_in[14];
    const float* cmuk = (const float*)d_in[15];
    const float* cWr  = (const float*)d_in[16];
    const float* cWk  = (const float*)d_in[17];
    const float* cWv  = (const float*)d_in[18];
    float* out = (float*)d_out;

    __half *hxr, *hxk, *hxv, *hr, *hk, *hv, *wh;
    cudaGetSymbolAddress((void**)&hxr, g_hxr);
    cudaGetSymbolAddress((void**)&hxk, g_hxk);
    cudaGetSymbolAddress((void**)&hxv, g_hxv);
    cudaGetSymbolAddress((void**)&hr,  g_hr);
    cudaGetSymbolAddress((void**)&hk,  g_hk);
    cudaGetSymbolAddress((void**)&hv,  g_hv);
    cudaGetSymbolAddress((void**)&wh,  g_wh);

    const size_t WOFF = 4194304;  // 2048*2048
    __half* wTr = wh + 0 * WOFF;
    __half* wTk = wh + 1 * WOFF;
    __half* wTv = wh + 2 * WOFF;
    __half* wTo = wh + 3 * WOFF;
    __half* wCr = wh + 4 * WOFF;
    __half* wCk = wh + 5 * WOFF;
    __half* wCv = wh + 6 * WOFF;

    cudaFuncSetAttribute(gemm_h<0>, cudaFuncAttributeMaxDynamicSharedMemorySize, GSM);
    cudaFuncSetAttribute(gemm_h<1>, cudaFuncAttributeMaxDynamicSharedMemorySize, GSM);
    cudaFuncSetAttribute(gemm_h<2>, cudaFuncAttributeMaxDynamicSharedMemorySize, GSM);
    cudaFuncSetAttribute(gemm_h<3>, cudaFuncAttributeMaxDynamicSharedMemorySize, GSM);

    const int EW = 32768;               // (16384*2048/4) / 256

    // ---- weight prep: all 7 fp32 -> fp16 in one launch ----
    WP wp;
    wp.s[0]=tWr; wp.s[1]=tWk; wp.s[2]=tWv; wp.s[3]=tWo; wp.s[4]=cWr; wp.s[5]=cWk; wp.s[6]=cWv;
    wp.d[0]=wTr; wp.d[1]=wTk; wp.d[2]=wTv; wp.d[3]=wTo; wp.d[4]=wCr; wp.d[5]=wCk; wp.d[6]=wCv;
    wprep_kernel<<<dim3(4096, 7), 256>>>(wp);

    dim3 gg1(MROWS / 128, DIMC / 256, 1);   // (128, 8, 1)

    // ---- time mixing ----
    lnmix_kernel<3><<<MROWS, 256>>>(x, ln1g, ln1b, tmur, tmuk, tmuv, hxr, hxk, hxv);
    {   // batched r,k,v GEMMs
        GB gb{};
        gb.A[0]=hxr; gb.A[1]=hxk; gb.A[2]=hxv;
        gb.W[0]=wTr; gb.W[1]=wTk; gb.W[2]=wTv;
        gb.C[0]=hr;  gb.C[1]=hk;  gb.C[2]=hv;
        gemm_h<0><<<dim3(128, 8, 3), 512, GSM>>>(gb);
    }
    wkv_kernel<<<EW, 256>>>(hr, hk, hv, tmu, hxr);   // z -> hxr
    {   // x2 = x + z @ Wout^T  (fp32 out)
        GB gb{};
        gb.A[0]=hxr; gb.W[0]=wTo; gb.C[0]=out; gb.aux=x;
        gemm_h<1><<<gg1, 512, GSM>>>(gb);
    }

    // ---- channel mixing ----
    lnmix_kernel<2><<<MROWS, 256>>>(out, ln2g, ln2b, cmur, cmuk, nullptr, hxr, hxk, nullptr);
    {   // batched r2 (plain) + k2 (relu^2) GEMMs
        GB gb{};
        gb.A[0]=hxr; gb.A[1]=hxk;
        gb.W[0]=wCr; gb.W[1]=wCk;
        gb.C[0]=hr;  gb.C[1]=hk;
        gemm_h<3><<<dim3(128, 8, 2), 512, GSM>>>(gb);
    }
    {   // out = x2 + sigmoid(r2) * (k2 @ Wv^T)
        GB gb{};
        gb.A[0]=hk; gb.W[0]=wCv; gb.C[0]=out; gb.aux=hr;
        gemm_h<2><<<gg1, 512, GSM>>>(gb);
    }
}

// round 16
// speedup vs baseline: 1.0490x; 1.0490x over previous
#include <cuda_runtime.h>
#include <cuda_fp16.h>
#include <cstdint>

// Problem dims
#define DIMC 2048
#define TT   2048
#define MROWS 16384            // B*T = 8*2048

// ---------------- scratch (static device globals; no dynamic alloc) ----------
__device__ __half g_hxr[33554432];   // mixed activations / wkv z
__device__ __half g_hxk[33554432];
__device__ __half g_hxv[33554432];
__device__ __half g_hr [33554432];   // GEMM outputs r / r2
__device__ __half g_hk [33554432];   // GEMM outputs k / relu(k2)^2
__device__ __half g_hv [33554432];   // GEMM output v
__device__ __half g_wh [7 * 4194304];   // 7 fp16 weight matrices

// ---------------- helpers ----------------------------------------------------
__device__ __forceinline__ uint32_t smem_u32(const void* p) {
    return (uint32_t)__cvta_generic_to_shared(p);
}
__device__ __forceinline__ void cp_async16(uint32_t saddr, const void* gptr) {
    asm volatile("cp.async.cg.shared.global [%0], [%1], 16;\n" :: "r"(saddr), "l"(gptr));
}
__device__ __forceinline__ float sigmoidf_(float x) {
    return 1.0f / (1.0f + expf(-x));
}
__device__ __forceinline__ uint32_t pack_h2(float a, float b) {
    __half2 h = __floats2half2_rn(a, b);
    return *(uint32_t*)&h;
}

// ---------------- fused LayerNorm + token-shift mix ---------------------------
template<int NOUT>
__global__ __launch_bounds__(256) void lnmix_kernel(
    const float* __restrict__ x, const float* __restrict__ g,
    const float* __restrict__ b,
    const float* __restrict__ mur, const float* __restrict__ muk,
    const float* __restrict__ muv,
    __half* __restrict__ xr, __half* __restrict__ xk, __half* __restrict__ xv)
{
    __shared__ float sred[32];
    int row = blockIdx.x;
    int tid = threadIdx.x;
    int t = row & (TT - 1);

    const float4* xp = (const float4*)(x + (size_t)row * DIMC);
    float4 v0 = xp[tid];
    float4 v1 = xp[tid + 256];
    float4 w0 = make_float4(0.f,0.f,0.f,0.f), w1 = w0;
    if (t > 0) {
        const float4* xq = (const float4*)(x + (size_t)(row - 1) * DIMC);
        w0 = xq[tid];
        w1 = xq[tid + 256];
    }
    float s0  = v0.x+v0.y+v0.z+v0.w + v1.x+v1.y+v1.z+v1.w;
    float ss0 = v0.x*v0.x+v0.y*v0.y+v0.z*v0.z+v0.w*v0.w
              + v1.x*v1.x+v1.y*v1.y+v1.z*v1.z+v1.w*v1.w;
    float s1  = w0.x+w0.y+w0.z+w0.w + w1.x+w1.y+w1.z+w1.w;
    float ss1 = w0.x*w0.x+w0.y*w0.y+w0.z*w0.z+w0.w*w0.w
              + w1.x*w1.x+w1.y*w1.y+w1.z*w1.z+w1.w*w1.w;
    #pragma unroll
    for (int o = 16; o > 0; o >>= 1) {
        s0  += __shfl_xor_sync(0xffffffffu, s0,  o);
        ss0 += __shfl_xor_sync(0xffffffffu, ss0, o);
        s1  += __shfl_xor_sync(0xffffffffu, s1,  o);
        ss1 += __shfl_xor_sync(0xffffffffu, ss1, o);
    }
    int wid = tid >> 5;
    if ((tid & 31) == 0) {
        sred[wid] = s0; sred[wid + 8] = ss0;
        sred[wid + 16] = s1; sred[wid + 24] = ss1;
    }
    __syncthreads();
    if (tid < 32) {
        float a = (tid < 8) ? sred[tid]      : 0.f;
        float c = (tid < 8) ? sred[tid + 8]  : 0.f;
        float d = (tid < 8) ? sred[tid + 16] : 0.f;
        float e = (tid < 8) ? sred[tid + 24] : 0.f;
        #pragma unroll
        for (int o = 4; o > 0; o >>= 1) {
            a += __shfl_xor_sync(0xffffffffu, a, o);
            c += __shfl_xor_sync(0xffffffffu, c, o);
            d += __shfl_xor_sync(0xffffffffu, d, o);
            e += __shfl_xor_sync(0xffffffffu, e, o);
        }
        if (tid == 0) { sred[0] = a; sred[1] = c; sred[2] = d; sred[3] = e; }
    }
    __syncthreads();
    float m0 = sred[0] * (1.0f / DIMC);
    float r0 = rsqrtf(sred[1] * (1.0f / DIMC) - m0 * m0 + 1e-5f);
    float m1 = sred[2] * (1.0f / DIMC);
    float r1 = rsqrtf(sred[3] * (1.0f / DIMC) - m1 * m1 + 1e-5f);
    float pf = (t > 0) ? 1.0f : 0.0f;   // hp = 0 at t==0

    const float4* gp = (const float4*)g;
    const float4* bp = (const float4*)b;
    uint2* xr2 = (uint2*)(xr + (size_t)row * DIMC);
    uint2* xk2 = (uint2*)(xk + (size_t)row * DIMC);
    uint2* xv2 = (uint2*)(xv + (size_t)row * DIMC);

    #pragma unroll
    for (int half_ = 0; half_ < 2; half_++) {
        int idx = tid + half_ * 256;
        float4 vv = half_ ? v1 : v0;
        float4 ww = half_ ? w1 : w0;
        float4 gg = gp[idx], bb = bp[idx];
        float4 h, hp;
        h.x = (vv.x - m0) * r0 * gg.x + bb.x;
        h.y = (vv.y - m0) * r0 * gg.y + bb.y;
        h.z = (vv.z - m0) * r0 * gg.z + bb.z;
        h.w = (vv.w - m0) * r0 * gg.w + bb.w;
        hp.x = ((ww.x - m1) * r1 * gg.x + bb.x) * pf;
        hp.y = ((ww.y - m1) * r1 * gg.y + bb.y) * pf;
        hp.z = ((ww.z - m1) * r1 * gg.z + bb.z) * pf;
        hp.w = ((ww.w - m1) * r1 * gg.w + bb.w) * pf;
        float4 mu, o;
        mu = ((const float4*)mur)[idx];
        o.x = mu.x*h.x + (1.f-mu.x)*hp.x;  o.y = mu.y*h.y + (1.f-mu.y)*hp.y;
        o.z = mu.z*h.z + (1.f-mu.z)*hp.z;  o.w = mu.w*h.w + (1.f-mu.w)*hp.w;
        xr2[idx] = make_uint2(pack_h2(o.x, o.y), pack_h2(o.z, o.w));
        mu = ((const float4*)muk)[idx];
        o.x = mu.x*h.x + (1.f-mu.x)*hp.x;  o.y = mu.y*h.y + (1.f-mu.y)*hp.y;
        o.z = mu.z*h.z + (1.f-mu.z)*hp.z;  o.w = mu.w*h.w + (1.f-mu.w)*hp.w;
        xk2[idx] = make_uint2(pack_h2(o.x, o.y), pack_h2(o.z, o.w));
        if (NOUT == 3) {
            mu = ((const float4*)muv)[idx];
            o.x = mu.x*h.x + (1.f-mu.x)*hp.x;  o.y = mu.y*h.y + (1.f-mu.y)*hp.y;
            o.z = mu.z*h.z + (1.f-mu.z)*hp.z;  o.w = mu.w*h.w + (1.f-mu.w)*hp.w;
            xv2[idx] = make_uint2(pack_h2(o.x, o.y), pack_h2(o.z, o.w));
        }
    }
}

// ---------------- wkv: z = sigmoid(r) * (e^{u+k} v)/(e^{u+k}+1e-8), all fp16 --
__global__ __launch_bounds__(256) void wkv_kernel(
    const __half* __restrict__ r, const __half* __restrict__ k,
    const __half* __restrict__ v, const float* __restrict__ u,
    __half* __restrict__ z)
{
    size_t i = (size_t)blockIdx.x * 256 + threadIdx.x;   // uint2 = 4 halves
    uint2 ru = ((const uint2*)r)[i];
    uint2 ku = ((const uint2*)k)[i];
    uint2 vu = ((const uint2*)v)[i];
    int c4 = (int)(i & 511);
    float4 uv = ((const float4*)u)[c4];
    float2 ra = __half22float2(*(__half2*)&ru.x), rb = __half22float2(*(__half2*)&ru.y);
    float2 ka = __half22float2(*(__half2*)&ku.x), kb = __half22float2(*(__half2*)&ku.y);
    float2 va = __half22float2(*(__half2*)&vu.x), vb = __half22float2(*(__half2*)&vu.y);
    float4 o;
    { float ek = expf(uv.x + ka.x); o.x = sigmoidf_(ra.x) * (ek * va.x) / (ek + 1e-8f); }
    { float ek = expf(uv.y + ka.y); o.y = sigmoidf_(ra.y) * (ek * va.y) / (ek + 1e-8f); }
    { float ek = expf(uv.z + kb.x); o.z = sigmoidf_(rb.x) * (ek * vb.x) / (ek + 1e-8f); }
    { float ek = expf(uv.w + kb.y); o.w = sigmoidf_(rb.y) * (ek * vb.y) / (ek + 1e-8f); }
    ((uint2*)z)[i] = make_uint2(pack_h2(o.x, o.y), pack_h2(o.z, o.w));
}

// ---------------- weight prep: fp32 -> fp16, all 7 matrices in one launch -----
struct WP { const float* s[7]; __half* d[7]; };
__global__ __launch_bounds__(256) void wprep_kernel(WP wp)
{
    int m = blockIdx.y;
    size_t i = (size_t)blockIdx.x * 256 + threadIdx.x;
    float4 v = ((const float4*)wp.s[m])[i];
    ((uint2*)wp.d[m])[i] = make_uint2(pack_h2(v.x, v.y), pack_h2(v.z, v.w));
}

// ---------------- fp16 GEMM: C[m,n] = sum_k A[m,k] * W[n,k] -------------------
// Block tile 128x128, K-chunk 64 halves (128B SW128 rows), 8 warps, warp 32x64,
// 2 CTAs/SM. 3 SMEM buffers, 2 chunks in flight, SINGLE __syncthreads/chunk:
// prologue issues 0,1; iter c: wait_group 1 (chunk c landed) -> barrier ->
// issue(c+2) into slot (c+2)%3 (distinct from slots of c, c+1; prior readers
// ordered by this barrier) -> compute slot c%3.
// gridDim.z batches independent GEMMs.
// MODE 0: C[z] = half(acc)
// MODE 1: C[0] = auxf + acc  (fp32)
// MODE 2: C[0] += sigmoid(auxh)*acc (fp32, in place)
// MODE 3: z==0: half(acc) ; z==1: half(relu(acc)^2)

#define KCH 64
#define NCCH (DIMC / KCH)           // 32 chunks
#define ASTG (128 * 128)
#define STGB (2 * ASTG)             // 32768
#define GSM  (3 * STGB)             // 98304

struct GB {
    const __half* A[3];
    const __half* W[3];
    void* C[3];
    const void* aux;
};

#define LDMX4(r0, r1, r2, r3, a) \
    asm volatile("ldmatrix.sync.aligned.m8n8.x4.shared.b16 {%0,%1,%2,%3}, [%4];" \
        : "=r"(r0), "=r"(r1), "=r"(r2), "=r"(r3) : "r"(a))

#define MMA16816(acc, a, b0, b1) \
    asm volatile( \
        "mma.sync.aligned.m16n8k16.row.col.f32.f16.f16.f32 " \
        "{%0,%1,%2,%3},{%4,%5,%6,%7},{%8,%9},{%0,%1,%2,%3};\n" \
        : "+f"((acc)[0]), "+f"((acc)[1]), "+f"((acc)[2]), "+f"((acc)[3]) \
        : "r"((a)[0]), "r"((a)[1]), "r"((a)[2]), "r"((a)[3]), "r"(b0), "r"(b1))

template<int MODE>
__global__ __launch_bounds__(256, 2) void gemm_h(GB gb)
{
    extern __shared__ char dsm[];
    uint32_t base = smem_u32(dsm);
    int tid  = threadIdx.x;
    int ln   = tid & 31;
    int wid  = tid >> 5;
    int z  = blockIdx.z;
    int bm = blockIdx.x * 128;
    int bn = blockIdx.y * 128;
    int mwarp = (wid & 3) * 32;
    int nwarp = (wid >> 2) * 64;

    const __half* A = gb.A[z];
    const __half* W = gb.W[z];

    float acc[2][8][4];
    #pragma unroll
    for (int i = 0; i < 2; i++)
        #pragma unroll
        for (int j = 0; j < 8; j++)
            #pragma unroll
            for (int q = 0; q < 4; q++) acc[i][j][q] = 0.f;

    auto issue = [&](int c) {
        uint32_t sb = base + (c % 3) * STGB;
        int kofs = c * KCH;
        #pragma unroll
        for (int j = 0; j < 4; j++) {
            int ch = tid + j * 256;
            int row = ch >> 3, seg = ch & 7;
            uint32_t off = row * 128 + seg * 16;
            uint32_t sw = off ^ ((off >> 3) & 0x70);
            cp_async16(sb + sw, A + (size_t)(bm + row) * DIMC + kofs + seg * 8);
        }
        #pragma unroll
        for (int j = 0; j < 4; j++) {
            int ch = tid + j * 256;
            int row = ch >> 3, seg = ch & 7;
            uint32_t off = row * 128 + seg * 16;
            uint32_t sw = off ^ ((off >> 3) & 0x70);
            cp_async16(sb + ASTG + sw, W + (size_t)(bn + row) * DIMC + kofs + seg * 8);
        }
        asm volatile("cp.async.commit_group;\n" ::: "memory");
    };

    issue(0); issue(1);

    int t4 = ln >> 3, r8 = ln & 7;
    int rA = (t4 & 1) * 8 + r8;
    int kA = (t4 >> 1) * 16;
    int rB = (t4 >> 1) * 8 + r8;
    int kB = (t4 & 1) * 16;

    for (int c = 0; c < NCCH; c++) {
        if (c < NCCH - 1) asm volatile("cp.async.wait_group 1;\n" ::: "memory");
        else              asm volatile("cp.async.wait_group 0;\n" ::: "memory");
        __syncthreads();
        if (c + 2 < NCCH) issue(c + 2);   // slot (c+2)%3: free, prior readers ordered

        uint32_t sb = base + (c % 3) * STGB;
        uint32_t ab = sb, bb = sb + ASTG;

        #pragma unroll
        for (int ks = 0; ks < 4; ks++) {
            uint32_t av[2][4];
            #pragma unroll
            for (int mt = 0; mt < 2; mt++) {
                int row = mwarp + mt * 16 + rA;
                uint32_t off = row * 128 + ks * 32 + kA;
                uint32_t sw = off ^ ((off >> 3) & 0x70);
                LDMX4(av[mt][0], av[mt][1], av[mt][2], av[mt][3], ab + sw);
            }
            uint32_t bv[4][4];
            #pragma unroll
            for (int np = 0; np < 4; np++) {
                int row = nwarp + np * 16 + rB;
                uint32_t off = row * 128 + ks * 32 + kB;
                uint32_t sw = off ^ ((off >> 3) & 0x70);
                LDMX4(bv[np][0], bv[np][1], bv[np][2], bv[np][3], bb + sw);
            }
            #pragma unroll
            for (int nt = 0; nt < 8; nt++) {
                uint32_t b0 = bv[nt >> 1][(nt & 1) * 2 + 0];
                uint32_t b1 = bv[nt >> 1][(nt & 1) * 2 + 1];
                MMA16816(acc[0][nt], av[0], b0, b1);
                MMA16816(acc[1][nt], av[1], b0, b1);
            }
        }
    }

    // ---------------- epilogue ----------------
    int rbase = bm + mwarp + (ln >> 2);
    int cbase = bn + nwarp + (ln & 3) * 2;
    #pragma unroll
    for (int mt = 0; mt < 2; mt++) {
        #pragma unroll
        for (int nt = 0; nt < 8; nt++) {
            int r0 = rbase + mt * 16;
            int cc = cbase + nt * 8;
            size_t i0 = (size_t)r0 * DIMC + cc;
            size_t i1 = i0 + (size_t)8 * DIMC;
            float2 p0 = make_float2(acc[mt][nt][0], acc[mt][nt][1]);
            float2 p1 = make_float2(acc[mt][nt][2], acc[mt][nt][3]);
            if (MODE == 0 || MODE == 3) {
                __half* Ch = (__half*)gb.C[z];
                if (MODE == 3 && z == 1) {
                    float a0 = fmaxf(p0.x, 0.f), a1 = fmaxf(p0.y, 0.f);
                    float a2 = fmaxf(p1.x, 0.f), a3 = fmaxf(p1.y, 0.f);
                    p0 = make_float2(a0 * a0, a1 * a1);
                    p1 = make_float2(a2 * a2, a3 * a3);
                }
                *(__half2*)(Ch + i0) = __floats2half2_rn(p0.x, p0.y);
                *(__half2*)(Ch + i1) = __floats2half2_rn(p1.x, p1.y);
            } else if (MODE == 1) {
                float* Cf = (float*)gb.C[0];
                const float* auxf = (const float*)gb.aux;
                float2 a0 = *(const float2*)(auxf + i0);
                float2 a1 = *(const float2*)(auxf + i1);
                p0.x += a0.x; p0.y += a0.y;
                p1.x += a1.x; p1.y += a1.y;
                *(float2*)(Cf + i0) = p0;
                *(float2*)(Cf + i1) = p1;
            } else {
                float* Cf = (float*)gb.C[0];
                const __half* auxh = (const __half*)gb.aux;
                float2 a0 = __half22float2(*(const __half2*)(auxh + i0));
                float2 a1 = __half22float2(*(const __half2*)(auxh + i1));
                float2 c0 = *(const float2*)(Cf + i0);
                float2 c1 = *(const float2*)(Cf + i1);
                p0.x = c0.x + sigmoidf_(a0.x) * p0.x;
                p0.y = c0.y + sigmoidf_(a0.y) * p0.y;
                p1.x = c1.x + sigmoidf_(a1.x) * p1.x;
                p1.y = c1.y + sigmoidf_(a1.y) * p1.y;
                *(float2*)(Cf + i0) = p0;
                *(float2*)(Cf + i1) = p1;
            }
        }
    }
}

// ---------------- host orchestration -----------------------------------------
extern "C" void kernel_launch(void* const* d_in, const int* in_sizes, int n_in,
                              void* d_out, int out_size)
{
    const float* x    = (const float*)d_in[0];
    const float* ln1g = (const float*)d_in[1];
    const float* ln1b = (const float*)d_in[2];
    const float* ln2g = (const float*)d_in[3];
    const float* ln2b = (const float*)d_in[4];
    // d_in[5] = tm_w (unused by the reference semantics)
    const float* tmu  = (const float*)d_in[6];
    const float* tmur = (const float*)d_in[7];
    const float* tmuk = (const float*)d_in[8];
    const float* tmuv = (const float*)d_in[9];
    const float* tWr  = (const float*)d_in[10];
    const float* tWk  = (const float*)d_in[11];
    const float* tWv  = (const float*)d_in[12];
    const float* tWo  = (const float*)d_in[13];
    const float* cmur = (const float*)d_in[14];
    const float* cmuk = (const float*)d_in[15];
    const float* cWr  = (const float*)d_in[16];
    const float* cWk  = (const float*)d_in[17];
    const float* cWv  = (const float*)d_in[18];
    float* out = (float*)d_out;

    __half *hxr, *hxk, *hxv, *hr, *hk, *hv, *wh;
    cudaGetSymbolAddress((void**)&hxr, g_hxr);
    cudaGetSymbolAddress((void**)&hxk, g_hxk);
    cudaGetSymbolAddress((void**)&hxv, g_hxv);
    cudaGetSymbolAddress((void**)&hr,  g_hr);
    cudaGetSymbolAddress((void**)&hk,  g_hk);
    cudaGetSymbolAddress((void**)&hv,  g_hv);
    cudaGetSymbolAddress((void**)&wh,  g_wh);

    const size_t WOFF = 4194304;  // 2048*2048
    __half* wTr = wh + 0 * WOFF;
    __half* wTk = wh + 1 * WOFF;
    __half* wTv = wh + 2 * WOFF;
    __half* wTo = wh + 3 * WOFF;
    __half* wCr = wh + 4 * WOFF;
    __half* wCk = wh + 5 * WOFF;
    __half* wCv = wh + 6 * WOFF;

    cudaFuncSetAttribute(gemm_h<0>, cudaFuncAttributeMaxDynamicSharedMemorySize, GSM);
    cudaFuncSetAttribute(gemm_h<1>, cudaFuncAttributeMaxDynamicSharedMemorySize, GSM);
    cudaFuncSetAttribute(gemm_h<2>, cudaFuncAttributeMaxDynamicSharedMemorySize, GSM);
    cudaFuncSetAttribute(gemm_h<3>, cudaFuncAttributeMaxDynamicSharedMemorySize, GSM);

    const int EW = 32768;               // (16384*2048/4) / 256

    // ---- weight prep: all 7 fp32 -> fp16 in one launch ----
    WP wp;
    wp.s[0]=tWr; wp.s[1]=tWk; wp.s[2]=tWv; wp.s[3]=tWo; wp.s[4]=cWr; wp.s[5]=cWk; wp.s[6]=cWv;
    wp.d[0]=wTr; wp.d[1]=wTk; wp.d[2]=wTv; wp.d[3]=wTo; wp.d[4]=wCr; wp.d[5]=wCk; wp.d[6]=wCv;
    wprep_kernel<<<dim3(4096, 7), 256>>>(wp);

    // ---- time mixing ----
    lnmix_kernel<3><<<MROWS, 256>>>(x, ln1g, ln1b, tmur, tmuk, tmuv, hxr, hxk, hxv);
    {   // batched r,k,v GEMMs
        GB gb{};
        gb.A[0]=hxr; gb.A[1]=hxk; gb.A[2]=hxv;
        gb.W[0]=wTr; gb.W[1]=wTk; gb.W[2]=wTv;
        gb.C[0]=hr;  gb.C[1]=hk;  gb.C[2]=hv;
        gemm_h<0><<<dim3(128, 16, 3), 256, GSM>>>(gb);
    }
    wkv_kernel<<<EW, 256>>>(hr, hk, hv, tmu, hxr);   // z -> hxr
    {   // x2 = x + z @ Wout^T  (fp32 out)
        GB gb{};
        gb.A[0]=hxr; gb.W[0]=wTo; gb.C[0]=out; gb.aux=x;
        gemm_h<1><<<dim3(128, 16, 1), 256, GSM>>>(gb);
    }

    // ---- channel mixing ----
    lnmix_kernel<2><<<MROWS, 256>>>(out, ln2g, ln2b, cmur, cmuk, nullptr, hxr, hxk, nullptr);
    {   // batched r2 (plain) + k2 (relu^2) GEMMs
        GB gb{};
        gb.A[0]=hxr; gb.A[1]=hxk;
        gb.W[0]=wCr; gb.W[1]=wCk;
        gb.C[0]=hr;  gb.C[1]=hk;
        gemm_h<3><<<dim3(128, 16, 2), 256, GSM>>>(gb);
    }
    {   // out = x2 + sigmoid(r2) * (k2 @ Wv^T)
        GB gb{};
        gb.A[0]=hk; gb.W[0]=wCv; gb.C[0]=out; gb.aux=hr;
        gemm_h<2><<<dim3(128, 16, 1), 256, GSM>>>(gb);
    }
}

// round 17
// speedup vs baseline: 1.0515x; 1.0024x over previous
#include <cuda_runtime.h>
#include <cuda_fp16.h>
#include <cstdint>

// Problem dims
#define DIMC 2048
#define TT   2048
#define MROWS 16384            // B*T = 8*2048

// ---------------- scratch (static device globals; no dynamic alloc) ----------
__device__ __half g_hxr[33554432];   // mixed activations / wkv z
__device__ __half g_hxk[33554432];
__device__ __half g_hxv[33554432];
__device__ __half g_hr [33554432];   // GEMM outputs r / r2
__device__ __half g_hk [33554432];   // GEMM outputs k / relu(k2)^2
__device__ __half g_hv [33554432];   // GEMM output v
__device__ __half g_wh [7 * 4194304];   // 7 fp16 weight matrices

// ---------------- helpers ----------------------------------------------------
__device__ __forceinline__ uint32_t smem_u32(const void* p) {
    return (uint32_t)__cvta_generic_to_shared(p);
}
__device__ __forceinline__ void cp_async16(uint32_t saddr, const void* gptr) {
    asm volatile("cp.async.cg.shared.global [%0], [%1], 16;\n" :: "r"(saddr), "l"(gptr));
}
__device__ __forceinline__ float sigmoidf_(float x) {
    return 1.0f / (1.0f + expf(-x));
}
__device__ __forceinline__ uint32_t pack_h2(float a, float b) {
    __half2 h = __floats2half2_rn(a, b);
    return *(uint32_t*)&h;
}

// ---------------- fused LayerNorm + token-shift mix ---------------------------
template<int NOUT>
__global__ __launch_bounds__(256) void lnmix_kernel(
    const float* __restrict__ x, const float* __restrict__ g,
    const float* __restrict__ b,
    const float* __restrict__ mur, const float* __restrict__ muk,
    const float* __restrict__ muv,
    __half* __restrict__ xr, __half* __restrict__ xk, __half* __restrict__ xv)
{
    __shared__ float sred[32];
    int row = blockIdx.x;
    int tid = threadIdx.x;
    int t = row & (TT - 1);

    const float4* xp = (const float4*)(x + (size_t)row * DIMC);
    float4 v0 = xp[tid];
    float4 v1 = xp[tid + 256];
    float4 w0 = make_float4(0.f,0.f,0.f,0.f), w1 = w0;
    if (t > 0) {
        const float4* xq = (const float4*)(x + (size_t)(row - 1) * DIMC);
        w0 = xq[tid];
        w1 = xq[tid + 256];
    }
    float s0  = v0.x+v0.y+v0.z+v0.w + v1.x+v1.y+v1.z+v1.w;
    float ss0 = v0.x*v0.x+v0.y*v0.y+v0.z*v0.z+v0.w*v0.w
              + v1.x*v1.x+v1.y*v1.y+v1.z*v1.z+v1.w*v1.w;
    float s1  = w0.x+w0.y+w0.z+w0.w + w1.x+w1.y+w1.z+w1.w;
    float ss1 = w0.x*w0.x+w0.y*w0.y+w0.z*w0.z+w0.w*w0.w
              + w1.x*w1.x+w1.y*w1.y+w1.z*w1.z+w1.w*w1.w;
    #pragma unroll
    for (int o = 16; o > 0; o >>= 1) {
        s0  += __shfl_xor_sync(0xffffffffu, s0,  o);
        ss0 += __shfl_xor_sync(0xffffffffu, ss0, o);
        s1  += __shfl_xor_sync(0xffffffffu, s1,  o);
        ss1 += __shfl_xor_sync(0xffffffffu, ss1, o);
    }
    int wid = tid >> 5;
    if ((tid & 31) == 0) {
        sred[wid] = s0; sred[wid + 8] = ss0;
        sred[wid + 16] = s1; sred[wid + 24] = ss1;
    }
    __syncthreads();
    if (tid < 32) {
        float a = (tid < 8) ? sred[tid]      : 0.f;
        float c = (tid < 8) ? sred[tid + 8]  : 0.f;
        float d = (tid < 8) ? sred[tid + 16] : 0.f;
        float e = (tid < 8) ? sred[tid + 24] : 0.f;
        #pragma unroll
        for (int o = 4; o > 0; o >>= 1) {
            a += __shfl_xor_sync(0xffffffffu, a, o);
            c += __shfl_xor_sync(0xffffffffu, c, o);
            d += __shfl_xor_sync(0xffffffffu, d, o);
            e += __shfl_xor_sync(0xffffffffu, e, o);
        }
        if (tid == 0) { sred[0] = a; sred[1] = c; sred[2] = d; sred[3] = e; }
    }
    __syncthreads();
    float m0 = sred[0] * (1.0f / DIMC);
    float r0 = rsqrtf(sred[1] * (1.0f / DIMC) - m0 * m0 + 1e-5f);
    float m1 = sred[2] * (1.0f / DIMC);
    float r1 = rsqrtf(sred[3] * (1.0f / DIMC) - m1 * m1 + 1e-5f);
    float pf = (t > 0) ? 1.0f : 0.0f;   // hp = 0 at t==0

    const float4* gp = (const float4*)g;
    const float4* bp = (const float4*)b;
    uint2* xr2 = (uint2*)(xr + (size_t)row * DIMC);
    uint2* xk2 = (uint2*)(xk + (size_t)row * DIMC);
    uint2* xv2 = (uint2*)(xv + (size_t)row * DIMC);

    #pragma unroll
    for (int half_ = 0; half_ < 2; half_++) {
        int idx = tid + half_ * 256;
        float4 vv = half_ ? v1 : v0;
        float4 ww = half_ ? w1 : w0;
        float4 gg = gp[idx], bb = bp[idx];
        float4 h, hp;
        h.x = (vv.x - m0) * r0 * gg.x + bb.x;
        h.y = (vv.y - m0) * r0 * gg.y + bb.y;
        h.z = (vv.z - m0) * r0 * gg.z + bb.z;
        h.w = (vv.w - m0) * r0 * gg.w + bb.w;
        hp.x = ((ww.x - m1) * r1 * gg.x + bb.x) * pf;
        hp.y = ((ww.y - m1) * r1 * gg.y + bb.y) * pf;
        hp.z = ((ww.z - m1) * r1 * gg.z + bb.z) * pf;
        hp.w = ((ww.w - m1) * r1 * gg.w + bb.w) * pf;
        float4 mu, o;
        mu = ((const float4*)mur)[idx];
        o.x = mu.x*h.x + (1.f-mu.x)*hp.x;  o.y = mu.y*h.y + (1.f-mu.y)*hp.y;
        o.z = mu.z*h.z + (1.f-mu.z)*hp.z;  o.w = mu.w*h.w + (1.f-mu.w)*hp.w;
        xr2[idx] = make_uint2(pack_h2(o.x, o.y), pack_h2(o.z, o.w));
        mu = ((const float4*)muk)[idx];
        o.x = mu.x*h.x + (1.f-mu.x)*hp.x;  o.y = mu.y*h.y + (1.f-mu.y)*hp.y;
        o.z = mu.z*h.z + (1.f-mu.z)*hp.z;  o.w = mu.w*h.w + (1.f-mu.w)*hp.w;
        xk2[idx] = make_uint2(pack_h2(o.x, o.y), pack_h2(o.z, o.w));
        if (NOUT == 3) {
            mu = ((const float4*)muv)[idx];
            o.x = mu.x*h.x + (1.f-mu.x)*hp.x;  o.y = mu.y*h.y + (1.f-mu.y)*hp.y;
            o.z = mu.z*h.z + (1.f-mu.z)*hp.z;  o.w = mu.w*h.w + (1.f-mu.w)*hp.w;
            xv2[idx] = make_uint2(pack_h2(o.x, o.y), pack_h2(o.z, o.w));
        }
    }
}

// ---------------- wkv: z = sigmoid(r) * (e^{u+k} v)/(e^{u+k}+1e-8), all fp16 --
__global__ __launch_bounds__(256) void wkv_kernel(
    const __half* __restrict__ r, const __half* __restrict__ k,
    const __half* __restrict__ v, const float* __restrict__ u,
    __half* __restrict__ z)
{
    size_t i = (size_t)blockIdx.x * 256 + threadIdx.x;   // uint2 = 4 halves
    uint2 ru = ((const uint2*)r)[i];
    uint2 ku = ((const uint2*)k)[i];
    uint2 vu = ((const uint2*)v)[i];
    int c4 = (int)(i & 511);
    float4 uv = ((const float4*)u)[c4];
    float2 ra = __half22float2(*(__half2*)&ru.x), rb = __half22float2(*(__half2*)&ru.y);
    float2 ka = __half22float2(*(__half2*)&ku.x), kb = __half22float2(*(__half2*)&ku.y);
    float2 va = __half22float2(*(__half2*)&vu.x), vb = __half22float2(*(__half2*)&vu.y);
    float4 o;
    { float ek = expf(uv.x + ka.x); o.x = sigmoidf_(ra.x) * (ek * va.x) / (ek + 1e-8f); }
    { float ek = expf(uv.y + ka.y); o.y = sigmoidf_(ra.y) * (ek * va.y) / (ek + 1e-8f); }
    { float ek = expf(uv.z + kb.x); o.z = sigmoidf_(rb.x) * (ek * vb.x) / (ek + 1e-8f); }
    { float ek = expf(uv.w + kb.y); o.w = sigmoidf_(rb.y) * (ek * vb.y) / (ek + 1e-8f); }
    ((uint2*)z)[i] = make_uint2(pack_h2(o.x, o.y), pack_h2(o.z, o.w));
}

// ---------------- weight prep: fp32 -> fp16, all 7 matrices in one launch -----
struct WP { const float* s[7]; __half* d[7]; };
__global__ __launch_bounds__(256) void wprep_kernel(WP wp)
{
    int m = blockIdx.y;
    size_t i = (size_t)blockIdx.x * 256 + threadIdx.x;
    float4 v = ((const float4*)wp.s[m])[i];
    ((uint2*)wp.d[m])[i] = make_uint2(pack_h2(v.x, v.y), pack_h2(v.z, v.w));
}

// ---------------- fp16 GEMM: C[m,n] = sum_k A[m,k] * W[n,k] -------------------
// Block tile 128x128, K-chunk 64 halves (128B SW128 rows), 8 warps, warp 32x64,
// 2 CTAs/SM. 3 SMEM buffers, 2 chunks in flight, SINGLE __syncthreads/chunk:
// prologue issues 0,1; iter c: wait_group 1 (chunk c landed) -> barrier ->
// issue(c+2) into slot (c+2)%3 (distinct from slots of c, c+1; prior readers
// ordered by this barrier) -> compute slot c%3.
// gridDim.z batches independent GEMMs.
// MODE 0: C[z] = half(acc)
// MODE 1: C[0] = auxf + acc  (fp32)
// MODE 2: C[0] += sigmoid(auxh)*acc (fp32, in place)
// MODE 3: z==0: half(acc) ; z==1: half(relu(acc)^2)

#define KCH 64
#define NCCH (DIMC / KCH)           // 32 chunks
#define ASTG (128 * 128)
#define STGB (2 * ASTG)             // 32768
#define GSM  (3 * STGB)             // 98304

struct GB {
    const __half* A[3];
    const __half* W[3];
    void* C[3];
    const void* aux;
};

#define LDMX4(r0, r1, r2, r3, a) \
    asm volatile("ldmatrix.sync.aligned.m8n8.x4.shared.b16 {%0,%1,%2,%3}, [%4];" \
        : "=r"(r0), "=r"(r1), "=r"(r2), "=r"(r3) : "r"(a))

#define MMA16816(acc, a, b0, b1) \
    asm volatile( \
        "mma.sync.aligned.m16n8k16.row.col.f32.f16.f16.f32 " \
        "{%0,%1,%2,%3},{%4,%5,%6,%7},{%8,%9},{%0,%1,%2,%3};\n" \
        : "+f"((acc)[0]), "+f"((acc)[1]), "+f"((acc)[2]), "+f"((acc)[3]) \
        : "r"((a)[0]), "r"((a)[1]), "r"((a)[2]), "r"((a)[3]), "r"(b0), "r"(b1))

template<int MODE>
__global__ __launch_bounds__(256, 2) void gemm_h(GB gb)
{
    extern __shared__ char dsm[];
    uint32_t base = smem_u32(dsm);
    int tid  = threadIdx.x;
    int ln   = tid & 31;
    int wid  = tid >> 5;
    int z  = blockIdx.z;
    int bm = blockIdx.x * 128;
    int bn = blockIdx.y * 128;
    int mwarp = (wid & 3) * 32;
    int nwarp = (wid >> 2) * 64;

    const __half* A = gb.A[z];
    const __half* W = gb.W[z];

    float acc[2][8][4];
    #pragma unroll
    for (int i = 0; i < 2; i++)
        #pragma unroll
        for (int j = 0; j < 8; j++)
            #pragma unroll
            for (int q = 0; q < 4; q++) acc[i][j][q] = 0.f;

    auto issue = [&](int c) {
        uint32_t sb = base + (c % 3) * STGB;
        int kofs = c * KCH;
        #pragma unroll
        for (int j = 0; j < 4; j++) {
            int ch = tid + j * 256;
            int row = ch >> 3, seg = ch & 7;
            uint32_t off = row * 128 + seg * 16;
            uint32_t sw = off ^ ((off >> 3) & 0x70);
            cp_async16(sb + sw, A + (size_t)(bm + row) * DIMC + kofs + seg * 8);
        }
        #pragma unroll
        for (int j = 0; j < 4; j++) {
            int ch = tid + j * 256;
            int row = ch >> 3, seg = ch & 7;
            uint32_t off = row * 128 + seg * 16;
            uint32_t sw = off ^ ((off >> 3) & 0x70);
            cp_async16(sb + ASTG + sw, W + (size_t)(bn + row) * DIMC + kofs + seg * 8);
        }
        asm volatile("cp.async.commit_group;\n" ::: "memory");
    };

    issue(0); issue(1);

    int t4 = ln >> 3, r8 = ln & 7;
    int rA = (t4 & 1) * 8 + r8;
    int kA = (t4 >> 1) * 16;
    int rB = (t4 >> 1) * 8 + r8;
    int kB = (t4 & 1) * 16;

    for (int c = 0; c < NCCH; c++) {
        if (c < NCCH - 1) asm volatile("cp.async.wait_group 1;\n" ::: "memory");
        else              asm volatile("cp.async.wait_group 0;\n" ::: "memory");
        __syncthreads();
        if (c + 2 < NCCH) issue(c + 2);   // slot (c+2)%3: free, prior readers ordered

        uint32_t sb = base + (c % 3) * STGB;
        uint32_t ab = sb, bb = sb + ASTG;

        #pragma unroll
        for (int ks = 0; ks < 4; ks++) {
            uint32_t av[2][4];
            #pragma unroll
            for (int mt = 0; mt < 2; mt++) {
                int row = mwarp + mt * 16 + rA;
                uint32_t off = row * 128 + ks * 32 + kA;
                uint32_t sw = off ^ ((off >> 3) & 0x70);
                LDMX4(av[mt][0], av[mt][1], av[mt][2], av[mt][3], ab + sw);
            }
            uint32_t bv[4][4];
            #pragma unroll
            for (int np = 0; np < 4; np++) {
                int row = nwarp + np * 16 + rB;
                uint32_t off = row * 128 + ks * 32 + kB;
                uint32_t sw = off ^ ((off >> 3) & 0x70);
                LDMX4(bv[np][0], bv[np][1], bv[np][2], bv[np][3], bb + sw);
            }
            #pragma unroll
            for (int nt = 0; nt < 8; nt++) {
                uint32_t b0 = bv[nt >> 1][(nt & 1) * 2 + 0];
                uint32_t b1 = bv[nt >> 1][(nt & 1) * 2 + 1];
                MMA16816(acc[0][nt], av[0], b0, b1);
                MMA16816(acc[1][nt], av[1], b0, b1);
            }
        }
    }

    // ---------------- epilogue ----------------
    int rbase = bm + mwarp + (ln >> 2);
    int cbase = bn + nwarp + (ln & 3) * 2;
    #pragma unroll
    for (int mt = 0; mt < 2; mt++) {
        #pragma unroll
        for (int nt = 0; nt < 8; nt++) {
            int r0 = rbase + mt * 16;
            int cc = cbase + nt * 8;
            size_t i0 = (size_t)r0 * DIMC + cc;
            size_t i1 = i0 + (size_t)8 * DIMC;
            float2 p0 = make_float2(acc[mt][nt][0], acc[mt][nt][1]);
            float2 p1 = make_float2(acc[mt][nt][2], acc[mt][nt][3]);
            if (MODE == 0 || MODE == 3) {
                __half* Ch = (__half*)gb.C[z];
                if (MODE == 3 && z == 1) {
                    float a0 = fmaxf(p0.x, 0.f), a1 = fmaxf(p0.y, 0.f);
                    float a2 = fmaxf(p1.x, 0.f), a3 = fmaxf(p1.y, 0.f);
                    p0 = make_float2(a0 * a0, a1 * a1);
                    p1 = make_float2(a2 * a2, a3 * a3);
                }
                *(__half2*)(Ch + i0) = __floats2half2_rn(p0.x, p0.y);
                *(__half2*)(Ch + i1) = __floats2half2_rn(p1.x, p1.y);
            } else if (MODE == 1) {
                float* Cf = (float*)gb.C[0];
                const float* auxf = (const float*)gb.aux;
                float2 a0 = *(const float2*)(auxf + i0);
                float2 a1 = *(const float2*)(auxf + i1);
                p0.x += a0.x; p0.y += a0.y;
                p1.x += a1.x; p1.y += a1.y;
                *(float2*)(Cf + i0) = p0;
                *(float2*)(Cf + i1) = p1;
            } else {
                float* Cf = (float*)gb.C[0];
                const __half* auxh = (const __half*)gb.aux;
                float2 a0 = __half22float2(*(const __half2*)(auxh + i0));
                float2 a1 = __half22float2(*(const __half2*)(auxh + i1));
                float2 c0 = *(const float2*)(Cf + i0);
                float2 c1 = *(const float2*)(Cf + i1);
                p0.x = c0.x + sigmoidf_(a0.x) * p0.x;
                p0.y = c0.y + sigmoidf_(a0.y) * p0.y;
                p1.x = c1.x + sigmoidf_(a1.x) * p1.x;
                p1.y = c1.y + sigmoidf_(a1.y) * p1.y;
                *(float2*)(Cf + i0) = p0;
                *(float2*)(Cf + i1) = p1;
            }
        }
    }
}

// ---------------- host orchestration -----------------------------------------
extern "C" void kernel_launch(void* const* d_in, const int* in_sizes, int n_in,
                              void* d_out, int out_size)
{
    const float* x    = (const float*)d_in[0];
    const float* ln1g = (const float*)d_in[1];
    const float* ln1b = (const float*)d_in[2];
    const float* ln2g = (const float*)d_in[3];
    const float* ln2b = (const float*)d_in[4];
    // d_in[5] = tm_w (unused by the reference semantics)
    const float* tmu  = (const float*)d_in[6];
    const float* tmur = (const float*)d_in[7];
    const float* tmuk = (const float*)d_in[8];
    const float* tmuv = (const float*)d_in[9];
    const float* tWr  = (const float*)d_in[10];
    const float* tWk  = (const float*)d_in[11];
    const float* tWv  = (const float*)d_in[12];
    const float* tWo  = (const float*)d_in[13];
    const float* cmur = (const float*)d_in[14];
    const float* cmuk = (const float*)d_in[15];
    const float* cWr  = (const float*)d_in[16];
    const float* cWk  = (const float*)d_in[17];
    const float* cWv  = (const float*)d_in[18];
    float* out = (float*)d_out;

    __half *hxr, *hxk, *hxv, *hr, *hk, *hv, *wh;
    cudaGetSymbolAddress((void**)&hxr, g_hxr);
    cudaGetSymbolAddress((void**)&hxk, g_hxk);
    cudaGetSymbolAddress((void**)&hxv, g_hxv);
    cudaGetSymbolAddress((void**)&hr,  g_hr);
    cudaGetSymbolAddress((void**)&hk,  g_hk);
    cudaGetSymbolAddress((void**)&hv,  g_hv);
    cudaGetSymbolAddress((void**)&wh,  g_wh);

    const size_t WOFF = 4194304;  // 2048*2048
    __half* wTr = wh + 0 * WOFF;
    __half* wTk = wh + 1 * WOFF;
    __half* wTv = wh + 2 * WOFF;
    __half* wTo = wh + 3 * WOFF;
    __half* wCr = wh + 4 * WOFF;
    __half* wCk = wh + 5 * WOFF;
    __half* wCv = wh + 6 * WOFF;

    cudaFuncSetAttribute(gemm_h<0>, cudaFuncAttributeMaxDynamicSharedMemorySize, GSM);
    cudaFuncSetAttribute(gemm_h<1>, cudaFuncAttributeMaxDynamicSharedMemorySize, GSM);
    cudaFuncSetAttribute(gemm_h<2>, cudaFuncAttributeMaxDynamicSharedMemorySize, GSM);
    cudaFuncSetAttribute(gemm_h<3>, cudaFuncAttributeMaxDynamicSharedMemorySize, GSM);

    const int EW = 32768;               // (16384*2048/4) / 256

    // ---- weight prep: all 7 fp32 -> fp16 in one launch ----
    WP wp;
    wp.s[0]=tWr; wp.s[1]=tWk; wp.s[2]=tWv; wp.s[3]=tWo; wp.s[4]=cWr; wp.s[5]=cWk; wp.s[6]=cWv;
    wp.d[0]=wTr; wp.d[1]=wTk; wp.d[2]=wTv; wp.d[3]=wTo; wp.d[4]=wCr; wp.d[5]=wCk; wp.d[6]=wCv;
    wprep_kernel<<<dim3(4096, 7), 256>>>(wp);

    // ---- time mixing ----
    lnmix_kernel<3><<<MROWS, 256>>>(x, ln1g, ln1b, tmur, tmuk, tmuv, hxr, hxk, hxv);
    {   // batched r,k,v GEMMs
        GB gb{};
        gb.A[0]=hxr; gb.A[1]=hxk; gb.A[2]=hxv;
        gb.W[0]=wTr; gb.W[1]=wTk; gb.W[2]=wTv;
        gb.C[0]=hr;  gb.C[1]=hk;  gb.C[2]=hv;
        gemm_h<0><<<dim3(128, 16, 3), 256, GSM>>>(gb);
    }
    wkv_kernel<<<EW, 256>>>(hr, hk, hv, tmu, hxr);   // z -> hxr
    {   // x2 = x + z @ Wout^T  (fp32 out)
        GB gb{};
        gb.A[0]=hxr; gb.W[0]=wTo; gb.C[0]=out; gb.aux=x;
        gemm_h<1><<<dim3(128, 16, 1), 256, GSM>>>(gb);
    }

    // ---- channel mixing ----
    lnmix_kernel<2><<<MROWS, 256>>>(out, ln2g, ln2b, cmur, cmuk, nullptr, hxr, hxk, nullptr);
    {   // batched r2 (plain) + k2 (relu^2) GEMMs
        GB gb{};
        gb.A[0]=hxr; gb.A[1]=hxk;
        gb.W[0]=wCr; gb.W[1]=wCk;
        gb.C[0]=hr;  gb.C[1]=hk;
        gemm_h<3><<<dim3(128, 16, 2), 256, GSM>>>(gb);
    }
    {   // out = x2 + sigmoid(r2) * (k2 @ Wv^T)
        GB gb{};
        gb.A[0]=hk; gb.W[0]=wCv; gb.C[0]=out; gb.aux=hr;
        gemm_h<2><<<dim3(128, 16, 1), 256, GSM>>>(gb);
    }
}